// round 2
// baseline (speedup 1.0000x reference)
#include <cuda_runtime.h>
#include <cuda_bf16.h>
#include <cstdint>
#include <cstddef>

#define VOCAB   100000
#define EMB     256
#define NS      256
#define BATCH   16384
#define MBLK    128
#define NBLOCKS (BATCH / MBLK)   // 128
#define KPAD    264              // bf16 elems per smem row (256 + 8 pad -> conflict-free ldmatrix)

__device__ float g_partials[NBLOCKS];

__device__ __forceinline__ float softplus_f(float x) {
    return fmaxf(x, 0.0f) + log1pf(expf(-fabsf(x)));
}

__device__ __forceinline__ uint32_t smem_u32(const void* p) {
    return (uint32_t)__cvta_generic_to_shared(p);
}

__device__ __forceinline__ void ldsm_x4(uint32_t& r0, uint32_t& r1, uint32_t& r2, uint32_t& r3,
                                        uint32_t addr) {
    asm volatile("ldmatrix.sync.aligned.m8n8.x4.shared.b16 {%0,%1,%2,%3}, [%4];"
                 : "=r"(r0), "=r"(r1), "=r"(r2), "=r"(r3) : "r"(addr));
}

__device__ __forceinline__ void ldsm_x2(uint32_t& r0, uint32_t& r1, uint32_t addr) {
    asm volatile("ldmatrix.sync.aligned.m8n8.x2.shared.b16 {%0,%1}, [%2];"
                 : "=r"(r0), "=r"(r1) : "r"(addr));
}

__device__ __forceinline__ void mma_bf16(float& c0, float& c1, float& c2, float& c3,
                                         uint32_t a0, uint32_t a1, uint32_t a2, uint32_t a3,
                                         uint32_t b0, uint32_t b1) {
    asm volatile("mma.sync.aligned.m16n8k16.row.col.f32.bf16.bf16.f32 "
                 "{%0,%1,%2,%3}, {%4,%5,%6,%7}, {%8,%9}, {%0,%1,%2,%3};"
                 : "+f"(c0), "+f"(c1), "+f"(c2), "+f"(c3)
                 : "r"(a0), "r"(a1), "r"(a2), "r"(a3), "r"(b0), "r"(b1));
}

__global__ void __launch_bounds__(256, 1) w2v_main(
    const float* __restrict__ emb,
    const float* __restrict__ ncew,
    const float* __restrict__ nceb,
    const int* __restrict__ inputs,
    const int* __restrict__ labels,
    const int* __restrict__ sids,
    float* __restrict__ out)
{
    extern __shared__ unsigned char smem_raw[];
    __nv_bfloat16* sA = (__nv_bfloat16*)smem_raw;           // [MBLK][KPAD]
    __nv_bfloat16* sW = sA + MBLK * KPAD;                   // [NS][KPAD]
    float* sCorr = (float*)(sW + (size_t)NS * KPAD);        // [NS]
    float* sPer  = sCorr + NS;                              // [MBLK]
    int*   sRow  = (int*)(sPer + MBLK);                     // [MBLK]

    const int tid  = threadIdx.x;
    const int bid  = blockIdx.x;
    const int row0 = bid * MBLK;
    const float INV_LOGV = 1.0f / logf((float)VOCAB + 1.0f);

    if (tid < MBLK) sRow[tid] = inputs[row0 + tid];
    if (tid < NS) {
        int s = sids[tid];
        float p = (logf((float)s + 2.0f) - logf((float)s + 1.0f)) * INV_LOGV;
        sCorr[tid] = nceb[s] - logf((float)NS * p);
    }
    __syncthreads();

    // ---- Gather embed rows: fp32 -> out (output 0), bf16 -> smem A tile ----
    for (int i = tid; i < MBLK * (EMB / 4); i += 256) {
        int r = i >> 6, c4 = i & 63;
        float4 v = __ldg((const float4*)(emb + (size_t)sRow[r] * EMB + c4 * 4));
        ((float4*)out)[(size_t)(row0 + r) * (EMB / 4) + c4] = v;
        __nv_bfloat162* d = (__nv_bfloat162*)(sA + r * KPAD + c4 * 4);
        d[0] = __floats2bfloat162_rn(v.x, v.y);
        d[1] = __floats2bfloat162_rn(v.z, v.w);
    }
    // ---- Gather sampled weight rows -> smem W tile (bf16) ----
    for (int i = tid; i < NS * (EMB / 4); i += 256) {
        int r = i >> 6, c4 = i & 63;
        int s = sids[r];
        float4 v = __ldg((const float4*)(ncew + (size_t)s * EMB + c4 * 4));
        __nv_bfloat162* d = (__nv_bfloat162*)(sW + r * KPAD + c4 * 4);
        d[0] = __floats2bfloat162_rn(v.x, v.y);
        d[1] = __floats2bfloat162_rn(v.z, v.w);
    }
    __syncthreads();

    const int warp = tid >> 5;
    const int lane = tid & 31;
    const int mrow = warp * 16;   // each of the 8 warps owns 16 batch rows

    // ---- True logits (full fp32, reading the just-written embed from L2) ----
    for (int rr = 0; rr < 16; rr++) {
        int r = mrow + rr;
        int lab = labels[row0 + r];
        const float* er = out  + (size_t)(row0 + r) * EMB;
        const float* wr = ncew + (size_t)lab * EMB;
        int e0 = lane * 8;
        float4 a0 = __ldg((const float4*)(er + e0));
        float4 a1 = __ldg((const float4*)(er + e0 + 4));
        float4 b0 = __ldg((const float4*)(wr + e0));
        float4 b1 = __ldg((const float4*)(wr + e0 + 4));
        float s = a0.x * b0.x;
        s = fmaf(a0.y, b0.y, s); s = fmaf(a0.z, b0.z, s); s = fmaf(a0.w, b0.w, s);
        s = fmaf(a1.x, b1.x, s); s = fmaf(a1.y, b1.y, s);
        s = fmaf(a1.z, b1.z, s); s = fmaf(a1.w, b1.w, s);
        #pragma unroll
        for (int o = 16; o; o >>= 1) s += __shfl_xor_sync(0xFFFFFFFFu, s, o);
        if (lane == 0) {
            float p = (logf((float)lab + 2.0f) - logf((float)lab + 1.0f)) * INV_LOGV;
            float t = s + nceb[lab] - logf((float)NS * p);
            sPer[r] = softplus_f(-t);   // sigmoid_xent(t, label=1)
        }
    }
    __syncwarp();

    // ---- Sampled logits: 16(rows) x 256(samples) per warp via bf16 HMMA ----
    float acc[32][4];
    #pragma unroll
    for (int n = 0; n < 32; n++) {
        acc[n][0] = 0.f; acc[n][1] = 0.f; acc[n][2] = 0.f; acc[n][3] = 0.f;
    }

    const int mi   = lane >> 3;             // ldmatrix sub-tile index
    const int l15  = lane & 15;
    const int arow = mrow + (mi & 1) * 8 + (lane & 7);
    const int acolb = (mi >> 1) * 8;
    const int brow_l = l15 & 7;
    const int bcolb  = (l15 >> 3) * 8;

    for (int k = 0; k < EMB; k += 16) {
        uint32_t a0, a1, a2, a3;
        ldsm_x4(a0, a1, a2, a3, smem_u32(sA + arow * KPAD + k + acolb));
        #pragma unroll
        for (int n = 0; n < 32; n++) {
            uint32_t b0, b1;
            ldsm_x2(b0, b1, smem_u32(sW + (n * 8 + brow_l) * KPAD + k + bcolb));
            mma_bf16(acc[n][0], acc[n][1], acc[n][2], acc[n][3], a0, a1, a2, a3, b0, b1);
        }
    }

    // ---- Epilogue: softplus(logit + corr) summed per row ----
    const int g = lane >> 2;   // row-in-8 group
    const int q = lane & 3;    // col pair selector
    float rs_lo = 0.f, rs_hi = 0.f;
    #pragma unroll
    for (int n = 0; n < 32; n++) {
        int c0 = n * 8 + q * 2;
        float k0 = sCorr[c0], k1 = sCorr[c0 + 1];
        rs_lo += softplus_f(acc[n][0] + k0) + softplus_f(acc[n][1] + k1);
        rs_hi += softplus_f(acc[n][2] + k0) + softplus_f(acc[n][3] + k1);
    }
    rs_lo += __shfl_xor_sync(0xFFFFFFFFu, rs_lo, 1);
    rs_lo += __shfl_xor_sync(0xFFFFFFFFu, rs_lo, 2);
    rs_hi += __shfl_xor_sync(0xFFFFFFFFu, rs_hi, 1);
    rs_hi += __shfl_xor_sync(0xFFFFFFFFu, rs_hi, 2);
    if (q == 0) {
        sPer[mrow + g]     += rs_lo;
        sPer[mrow + 8 + g] += rs_hi;
    }
    __syncthreads();

    // ---- Deterministic block reduction -> per-block partial ----
    if (tid < MBLK) {
        float v = sPer[tid];
        #pragma unroll
        for (int o = 16; o; o >>= 1) v += __shfl_xor_sync(0xFFFFFFFFu, v, o);
        if ((tid & 31) == 0) sCorr[tid >> 5] = v;   // reuse sCorr as scratch
    }
    __syncthreads();
    if (tid == 0) g_partials[bid] = sCorr[0] + sCorr[1] + sCorr[2] + sCorr[3];
}

__global__ void w2v_final(float* __restrict__ out) {
    int tid = threadIdx.x;               // 128 threads
    float v = g_partials[tid];
    #pragma unroll
    for (int o = 16; o; o >>= 1) v += __shfl_xor_sync(0xFFFFFFFFu, v, o);
    __shared__ float ws[4];
    if ((tid & 31) == 0) ws[tid >> 5] = v;
    __syncthreads();
    if (tid == 0)
        out[(size_t)BATCH * EMB] = (ws[0] + ws[1] + ws[2] + ws[3]) * (1.0f / (float)BATCH);
}

extern "C" void kernel_launch(void* const* d_in, const int* in_sizes, int n_in,
                              void* d_out, int out_size) {
    const float* emb    = (const float*)d_in[0];
    const float* ncew   = (const float*)d_in[1];
    const float* nceb   = (const float*)d_in[2];
    const int*   inputs = (const int*)d_in[3];
    const int*   labels = (const int*)d_in[4];
    const int*   sids   = (const int*)d_in[5];
    float* out = (float*)d_out;

    size_t smem = (size_t)(MBLK + NS) * KPAD * sizeof(__nv_bfloat16)   // A + W tiles
                + (size_t)NS * sizeof(float)                            // corr
                + (size_t)MBLK * sizeof(float)                          // per-row
                + (size_t)MBLK * sizeof(int);                           // row ids
    cudaFuncSetAttribute(w2v_main, cudaFuncAttributeMaxDynamicSharedMemorySize, (int)smem);

    w2v_main<<<NBLOCKS, 256, smem>>>(emb, ncew, nceb, inputs, labels, sids, out);
    w2v_final<<<1, 128>>>(out);
}

// round 3
// speedup vs baseline: 1.3268x; 1.3268x over previous
#include <cuda_runtime.h>
#include <cuda_bf16.h>
#include <cstdint>
#include <cstddef>

#define VOCAB   100000
#define EMB     256
#define NS      256
#define BATCH   16384
#define MBLK    64               // batch rows per block
#define NSB     128              // sampled columns per block
#define NSPLIT  (NS / NSB)       // 2
#define NBLK    ((BATCH / MBLK) * NSPLIT)   // 512
#define KPAD    264              // bf16 elems per smem row (256+8 -> conflict-free ldmatrix)

__device__ float g_partials[NBLK];
__device__ int   g_count = 0;

__device__ __forceinline__ float softplus_fast(float x) {
    return fmaxf(x, 0.0f) + __logf(1.0f + __expf(-fabsf(x)));
}

__device__ __forceinline__ uint32_t smem_u32(const void* p) {
    return (uint32_t)__cvta_generic_to_shared(p);
}

__device__ __forceinline__ void ldsm_x4(uint32_t& r0, uint32_t& r1, uint32_t& r2, uint32_t& r3,
                                        uint32_t addr) {
    asm volatile("ldmatrix.sync.aligned.m8n8.x4.shared.b16 {%0,%1,%2,%3}, [%4];"
                 : "=r"(r0), "=r"(r1), "=r"(r2), "=r"(r3) : "r"(addr));
}

__device__ __forceinline__ void mma_bf16(float& c0, float& c1, float& c2, float& c3,
                                         uint32_t a0, uint32_t a1, uint32_t a2, uint32_t a3,
                                         uint32_t b0, uint32_t b1) {
    asm volatile("mma.sync.aligned.m16n8k16.row.col.f32.bf16.bf16.f32 "
                 "{%0,%1,%2,%3}, {%4,%5,%6,%7}, {%8,%9}, {%0,%1,%2,%3};"
                 : "+f"(c0), "+f"(c1), "+f"(c2), "+f"(c3)
                 : "r"(a0), "r"(a1), "r"(a2), "r"(a3), "r"(b0), "r"(b1));
}

__global__ void __launch_bounds__(256, 2) w2v_fused(
    const float* __restrict__ emb,
    const float* __restrict__ ncew,
    const float* __restrict__ nceb,
    const int* __restrict__ inputs,
    const int* __restrict__ labels,
    const int* __restrict__ sids,
    float* __restrict__ out)
{
    extern __shared__ unsigned char smem_raw[];
    __nv_bfloat16* sA = (__nv_bfloat16*)smem_raw;             // [MBLK][KPAD]
    __nv_bfloat16* sW = sA + MBLK * KPAD;                     // [NSB][KPAD]
    float* sCorr = (float*)(sW + (size_t)NSB * KPAD);         // [NSB]
    int*   sRow  = (int*)(sCorr + NSB);                       // [MBLK]
    float* sRed  = (float*)(sRow + MBLK);                     // [8]

    const int tid  = threadIdx.x;
    const int bid  = blockIdx.x;
    const int rb   = bid >> 1;            // row-block 0..255
    const int ns   = bid & 1;             // sample half 0/1
    const int row0 = rb * MBLK;
    const int s0   = ns * NSB;
    const float INV_LOGV = 1.0f / logf((float)VOCAB + 1.0f);

    if (tid < MBLK) sRow[tid] = inputs[row0 + tid];
    if (tid < NSB) {
        int s = sids[s0 + tid];
        float p = (logf((float)s + 2.0f) - logf((float)s + 1.0f)) * INV_LOGV;
        sCorr[tid] = nceb[s] - logf((float)NS * p);
    }
    __syncthreads();

    // ---- Gather embed rows: fp32 -> out (my half of rows), bf16 -> smem A ----
    #pragma unroll
    for (int it = 0; it < MBLK * (EMB / 4) / 256; it++) {
        int i = it * 256 + tid;
        int r = i >> 6, c4 = i & 63;
        float4 v = __ldg((const float4*)(emb + (size_t)sRow[r] * EMB + c4 * 4));
        if ((r >> 5) == ns)   // each sample-half block stores 32 of the 64 rows
            ((float4*)out)[(size_t)(row0 + r) * (EMB / 4) + c4] = v;
        __nv_bfloat162* d = (__nv_bfloat162*)(sA + r * KPAD + c4 * 4);
        d[0] = __floats2bfloat162_rn(v.x, v.y);
        d[1] = __floats2bfloat162_rn(v.z, v.w);
    }
    // ---- Gather my 128 sampled weight rows -> smem W (bf16) ----
    #pragma unroll
    for (int it = 0; it < NSB * (EMB / 4) / 256; it++) {
        int i = it * 256 + tid;
        int r = i >> 6, c4 = i & 63;
        int s = sids[s0 + r];
        float4 v = __ldg((const float4*)(ncew + (size_t)s * EMB + c4 * 4));
        __nv_bfloat162* d = (__nv_bfloat162*)(sW + r * KPAD + c4 * 4);
        d[0] = __floats2bfloat162_rn(v.x, v.y);
        d[1] = __floats2bfloat162_rn(v.z, v.w);
    }

    const int warp = tid >> 5;
    const int lane = tid & 31;

    // ---- True logits: this block handles 32 of its 64 rows (4 per warp) ----
    // (reads emb rows again: L1-hot from the gather above; independent of smem)
    float tacc = 0.0f;
    #pragma unroll
    for (int i = 0; i < 4; i++) {
        int lr = ns * 32 + warp * 4 + i;
        int gr = row0 + lr;
        int lab = labels[gr];
        const float* er = emb  + (size_t)sRow[lr] * EMB;
        const float* wr = ncew + (size_t)lab * EMB;
        int e0 = lane * 8;
        float4 a0 = __ldg((const float4*)(er + e0));
        float4 a1 = __ldg((const float4*)(er + e0 + 4));
        float4 b0 = __ldg((const float4*)(wr + e0));
        float4 b1 = __ldg((const float4*)(wr + e0 + 4));
        float s = a0.x * b0.x;
        s = fmaf(a0.y, b0.y, s); s = fmaf(a0.z, b0.z, s); s = fmaf(a0.w, b0.w, s);
        s = fmaf(a1.x, b1.x, s); s = fmaf(a1.y, b1.y, s);
        s = fmaf(a1.z, b1.z, s); s = fmaf(a1.w, b1.w, s);
        #pragma unroll
        for (int o = 16; o; o >>= 1) s += __shfl_xor_sync(0xFFFFFFFFu, s, o);
        if (lane == 0) {
            float p = (logf((float)lab + 2.0f) - logf((float)lab + 1.0f)) * INV_LOGV;
            float t = s + nceb[lab] - logf((float)NS * p);
            tacc += softplus_fast(-t);    // sigmoid_xent(t, 1)
        }
    }
    __syncthreads();

    // ---- Sampled logits: warp (wm, wn) owns 16 rows x 64 samples ----
    const int wm = warp & 3;
    const int wn = warp >> 2;
    const int mrow  = wm * 16;
    const int nbase = wn * 64;

    float acc[8][4];
    #pragma unroll
    for (int n = 0; n < 8; n++) {
        acc[n][0] = 0.f; acc[n][1] = 0.f; acc[n][2] = 0.f; acc[n][3] = 0.f;
    }

    const int mi = lane >> 3;   // ldmatrix sub-tile index 0..3
    const int arow = mrow + (mi & 1) * 8 + (lane & 7);
    const int acolb = (mi >> 1) * 8;
    const int bRow = nbase + (mi >> 1) * 8 + (lane & 7);   // +nn*16 inside loop
    const int bcolb = (mi & 1) * 8;

    #pragma unroll
    for (int k = 0; k < EMB; k += 16) {
        uint32_t a0, a1, a2, a3;
        ldsm_x4(a0, a1, a2, a3, smem_u32(sA + arow * KPAD + k + acolb));
        #pragma unroll
        for (int nn = 0; nn < 4; nn++) {
            uint32_t b0, b1, b2, b3;   // {b0,b1}=n-tile 2nn, {b2,b3}=n-tile 2nn+1
            ldsm_x4(b0, b1, b2, b3, smem_u32(sW + (bRow + nn * 16) * KPAD + k + bcolb));
            mma_bf16(acc[2*nn  ][0], acc[2*nn  ][1], acc[2*nn  ][2], acc[2*nn  ][3],
                     a0, a1, a2, a3, b0, b1);
            mma_bf16(acc[2*nn+1][0], acc[2*nn+1][1], acc[2*nn+1][2], acc[2*nn+1][3],
                     a0, a1, a2, a3, b2, b3);
        }
    }

    // ---- Epilogue: fast softplus(logit + corr), thread-local sum ----
    const int q = lane & 3;
    float local = tacc;
    #pragma unroll
    for (int n = 0; n < 8; n++) {
        int c0 = nbase + n * 8 + q * 2;
        float k0 = sCorr[c0], k1 = sCorr[c0 + 1];
        local += softplus_fast(acc[n][0] + k0) + softplus_fast(acc[n][1] + k1)
               + softplus_fast(acc[n][2] + k0) + softplus_fast(acc[n][3] + k1);
    }

    // ---- Deterministic block reduction -> per-block partial ----
    #pragma unroll
    for (int o = 16; o; o >>= 1) local += __shfl_xor_sync(0xFFFFFFFFu, local, o);
    if (lane == 0) sRed[warp] = local;
    __syncthreads();
    __shared__ bool sLast;
    if (tid == 0) {
        float v = 0.f;
        #pragma unroll
        for (int w = 0; w < 8; w++) v += sRed[w];
        g_partials[bid] = v;
        __threadfence();
        int old = atomicAdd(&g_count, 1);
        sLast = (old == NBLK - 1);
    }
    __syncthreads();

    // ---- Last block folds all partials into the scalar (deterministic tree) ----
    if (sLast) {
        __threadfence();
        float v = g_partials[tid] + g_partials[tid + 256];
        #pragma unroll
        for (int o = 16; o; o >>= 1) v += __shfl_xor_sync(0xFFFFFFFFu, v, o);
        if (lane == 0) sRed[warp] = v;
        __syncthreads();
        if (tid == 0) {
            float t = 0.f;
            #pragma unroll
            for (int w = 0; w < 8; w++) t += sRed[w];
            out[(size_t)BATCH * EMB] = t * (1.0f / (float)BATCH);
            g_count = 0;   // reset for next graph replay
        }
    }
}

extern "C" void kernel_launch(void* const* d_in, const int* in_sizes, int n_in,
                              void* d_out, int out_size) {
    const float* emb    = (const float*)d_in[0];
    const float* ncew   = (const float*)d_in[1];
    const float* nceb   = (const float*)d_in[2];
    const int*   inputs = (const int*)d_in[3];
    const int*   labels = (const int*)d_in[4];
    const int*   sids   = (const int*)d_in[5];
    float* out = (float*)d_out;

    size_t smem = (size_t)(MBLK + NSB) * KPAD * sizeof(__nv_bfloat16)
                + (size_t)NSB * sizeof(float)
                + (size_t)MBLK * sizeof(int)
                + 8 * sizeof(float);
    cudaFuncSetAttribute(w2v_fused, cudaFuncAttributeMaxDynamicSharedMemorySize, (int)smem);
    w2v_fused<<<NBLK, 256, smem>>>(emb, ncew, nceb, inputs, labels, sids, out);
}